// round 6
// baseline (speedup 1.0000x reference)
#include <cuda_runtime.h>
#include <cuda_fp16.h>
#include <math.h>
#include <stdint.h>

#define NPTS   400000
#define K27    27
#define TM     128
#define NTILES 3125     // 400000 / 128 exact
#define NPAD   40       // padded C_out (5 n-blocks of 8)

// ---------------- global scratch (static; no allocation allowed) ----------------
__device__ __half g_f16[(size_t)NPTS * 64];     // features fp16
__device__ __half g_h  [(size_t)NPTS * 48];     // layer-1 activations fp16, padded to 48
__device__ uint2  g_W1f[27 * 5 * 4 * 32];       // fragment-packed W1: [k][nb][ch][lane]
__device__ uint2  g_W2f[27 * 5 * 3 * 32];       // fragment-packed W2

// ---------------- helpers ----------------
__device__ __forceinline__ void cpa16(void* dst_smem, const void* src) {
    uint32_t d = (uint32_t)__cvta_generic_to_shared(dst_smem);
    asm volatile("cp.async.ca.shared.global [%0], [%1], 16;" :: "r"(d), "l"(src));
}
#define CP_COMMIT() asm volatile("cp.async.commit_group;" ::: "memory")
#define CP_WAIT(n)  asm volatile("cp.async.wait_group %0;" :: "n"(n) : "memory")

// smem layout offsets (bytes)
#define OFF_D     0                        // 128*40*4 = 20480
#define OFF_PAIRS 20480                    // 27*128*4 = 13824
#define OFF_CNT   34304                    // 27 ints (pad 128)
#define OFF_BCNT  34432                    // 32 ints
#define OFF_BLK   34560                    // 32*8 ints = 1024
#define OFF_NB    35584                    // 1 int (pad to 128)
#define OFF_A     35712                    // 3 stages * 128 * ASTR halves

// ---------------- fused sparse-conv layer ----------------
// CIN: fp16 row width (64 or 48), KCH: k16 chunks (4 or 3)
template<int CIN, int KCH, bool DO_GELU>
__global__ void __launch_bounds__(256, 2) conv_mma(
    const __half* __restrict__ in, const int* __restrict__ nbr,
    const uint2* __restrict__ Wf, void* __restrict__ outp)
{
    constexpr int NCH  = CIN / 8;     // 16B chunks per row
    constexpr int ASTR = CIN + 8;     // +16B pad -> conflict-free frag LDS

    extern __shared__ char smem[];
    float* sD     = (float*)(smem + OFF_D);
    int*   sPairs = (int*)  (smem + OFF_PAIRS);
    int*   sCnt   = (int*)  (smem + OFF_CNT);
    int*   sBCnt  = (int*)  (smem + OFF_BCNT);
    int*   sBlk   = (int*)  (smem + OFF_BLK);
    int*   sNB    = (int*)  (smem + OFF_NB);
    __half* sA    = (__half*)(smem + OFF_A);

    const int tid  = threadIdx.x;
    const int lane = tid & 31;
    const int warp = tid >> 5;
    const int base = blockIdx.x * TM;

    // zero accumulators
    for (int e = tid; e < TM * NPAD; e += 256) sD[e] = 0.0f;

    // ---- compaction: per-offset valid (dst,src) lists via ballots ----
    for (int k = warp; k < K27; k += 8) {
        int cnt = 0;
        const int* np = nbr + (size_t)k * NPTS + base;
        #pragma unroll
        for (int j = 0; j < 4; j++) {
            int i   = j * 32 + lane;
            int src = np[i];
            bool v  = (src != NPTS);
            unsigned m = __ballot_sync(0xFFFFFFFFu, v);
            if (v) sPairs[k * 128 + cnt + __popc(m & ((1u << lane) - 1u))] = (i << 20) | src;
            cnt += __popc(m);
        }
        if (lane == 0) sCnt[k] = cnt;
    }
    __syncthreads();

    // ---- batch planner: pack 16-row blocks (<=8 per batch = 128 rows) ----
    if (tid == 0) {
        int nbatch = 0, cur = 0;
        for (int k = 0; k < K27; k++) {
            int c = sCnt[k];
            if (!c) continue;
            int blocks = (c + 15) >> 4;
            if (cur + blocks > 8) { sBCnt[nbatch++] = cur; cur = 0; }
            for (int b = 0; b < blocks; b++) sBlk[nbatch * 8 + cur + b] = (k << 8) | b;
            cur += blocks;
        }
        if (cur) { sBCnt[nbatch++] = cur; }
        sNB[0] = nbatch;
    }
    __syncthreads();
    const int nB = sNB[0];

    // ---- producer: gather one batch's rows into stage buffer ----
    auto issue = [&](int b) {
        if (b < nB) {
            int bcnt = sBCnt[b];
            __half* Ab = sA + (b % 3) * TM * ASTR;
            for (int e = tid; e < bcnt * 16 * NCH; e += 256) {
                int r = e / NCH, ch = e - r * NCH;
                int desc = sBlk[b * 8 + (r >> 4)];
                int k = desc >> 8, p = (desc & 255) * 16 + (r & 15);
                if (p < sCnt[k]) {
                    int src = sPairs[k * 128 + p] & 0xFFFFF;
                    cpa16(Ab + r * ASTR + ch * 8, in + (size_t)src * CIN + ch * 8);
                } else {
                    *(uint4*)(Ab + r * ASTR + ch * 8) = make_uint4(0, 0, 0, 0);
                }
            }
        }
        CP_COMMIT();   // always commit (empty group keeps wait_group counts exact)
    };

    issue(0); issue(1);

    const int gid = lane >> 2;   // fragment row group 0..7
    const int tg  = lane & 3;    // fragment col group 0..3

    for (int b = 0; b < nB; b++) {
        __syncthreads();                 // compute(b-1) done -> stage (b+2)%3 free
        issue(b + 2);
        CP_WAIT(2);                      // batch b's data landed
        __syncthreads();

        const int bcnt = sBCnt[b];
        const __half* Ab = sA + (b % 3) * TM * ASTR;
        const int units = bcnt * 5;
        for (int u = warp; u < units; u += 8) {
            const int s = u / 5, nb = u - s * 5;
            const int desc = sBlk[b * 8 + s];
            const int k = desc >> 8, blk = desc & 255;
            const int r0 = s * 16 + gid, r1 = r0 + 8;

            const uint2* wp = Wf + (size_t)(k * 5 + nb) * KCH * 32 + lane;
            float c0 = 0.f, c1 = 0.f, c2 = 0.f, c3 = 0.f;
            #pragma unroll
            for (int ch = 0; ch < KCH; ch++) {
                const int k0 = ch * 16 + tg * 2;
                uint2 bb = wp[ch * 32];
                uint32_t a0 = *(const uint32_t*)(Ab + r0 * ASTR + k0);
                uint32_t a1 = *(const uint32_t*)(Ab + r1 * ASTR + k0);
                uint32_t a2 = *(const uint32_t*)(Ab + r0 * ASTR + k0 + 8);
                uint32_t a3 = *(const uint32_t*)(Ab + r1 * ASTR + k0 + 8);
                asm volatile(
                    "mma.sync.aligned.m16n8k16.row.col.f32.f16.f16.f32 "
                    "{%0,%1,%2,%3}, {%4,%5,%6,%7}, {%8,%9}, {%0,%1,%2,%3};"
                    : "+f"(c0), "+f"(c1), "+f"(c2), "+f"(c3)
                    : "r"(a0), "r"(a1), "r"(a2), "r"(a3), "r"(bb.x), "r"(bb.y));
            }
            const int cnt_k = sCnt[k];
            const int col = nb * 8 + tg * 2;
            const int p0 = blk * 16 + gid, p1 = p0 + 8;
            if (p0 < cnt_k) {
                int d = ((unsigned)sPairs[k * 128 + p0]) >> 20;
                atomicAdd(&sD[d * NPAD + col], c0);
                atomicAdd(&sD[d * NPAD + col + 1], c1);
            }
            if (p1 < cnt_k) {
                int d = ((unsigned)sPairs[k * 128 + p1]) >> 20;
                atomicAdd(&sD[d * NPAD + col], c2);
                atomicAdd(&sD[d * NPAD + col + 1], c3);
            }
        }
    }
    __syncthreads();

    // ---- epilogue ----
    if (DO_GELU) {
        __half2* hp = (__half2*)outp;
        for (int e = tid; e < TM * 24; e += 256) {   // 24 half2 = 48 halves per row
            int r = e / 24, c2i = e - r * 24;
            int c = c2i * 2;
            float x0 = (c     < NPAD) ? sD[r * NPAD + c]     : 0.0f;
            float x1 = (c + 1 < NPAD) ? sD[r * NPAD + c + 1] : 0.0f;
            x0 *= normcdff(x0); x1 *= normcdff(x1);
            hp[(size_t)(base + r) * 24 + c2i] = __floats2half2_rn(x0, x1);
        }
    } else {
        float* op = (float*)outp + (size_t)base * 38;
        for (int e = tid; e < TM * 38; e += 256) {
            int r = e / 38, c = e - r * 38;
            op[e] = sD[r * NPAD + c];
        }
    }
}

// ---------------- one-time conversions ----------------
__global__ void cvt_feat(const float* __restrict__ f) {
    size_t i = (size_t)blockIdx.x * blockDim.x + threadIdx.x;
    const size_t n4 = (size_t)NPTS * 64 / 4;
    if (i < n4) {
        float4 v = ((const float4*)f)[i];
        __half2* o = (__half2*)g_f16;
        o[i * 2 + 0] = __floats2half2_rn(v.x, v.y);
        o[i * 2 + 1] = __floats2half2_rn(v.z, v.w);
    }
}

// fragment packing: per (k, nb, ch, lane): n = nb*8 + lane/4, kk0 = ch*16 + (lane%4)*2
// b0 = (W[kk0][n], W[kk0+1][n]); b1 = (W[kk0+8][n], W[kk0+9][n])
template<int KW, int KCH>
__device__ __forceinline__ void pack_one(const float* W, uint2* Wf, int i) {
    int lane = i & 31, ch = (i >> 5) % KCH, nb = (i / (32 * KCH)) % 5, k = i / (32 * KCH * 5);
    int n = nb * 8 + (lane >> 2);
    int kk0 = ch * 16 + (lane & 3) * 2;
    const float* Wk = W + (size_t)k * KW * 38;
    auto val = [&](int kk) -> float {
        return (n < 38 && kk < KW) ? Wk[kk * 38 + n] : 0.0f;
    };
    __half2 b0 = __floats2half2_rn(val(kk0),     val(kk0 + 1));
    __half2 b1 = __floats2half2_rn(val(kk0 + 8), val(kk0 + 9));
    Wf[i] = make_uint2(*(uint32_t*)&b0, *(uint32_t*)&b1);
}
__global__ void cvt_w(const float* __restrict__ W1, const float* __restrict__ W2) {
    int i = blockIdx.x * blockDim.x + threadIdx.x;
    if (i < 27 * 5 * 4 * 32) pack_one<64, 4>(W1, g_W1f, i);
    if (i < 27 * 5 * 3 * 32) pack_one<38, 3>(W2, g_W2f, i);
}

extern "C" void kernel_launch(void* const* d_in, const int* in_sizes, int n_in,
                              void* d_out, int out_size)
{
    const float* feat = nullptr;
    const int*   nbr  = nullptr;
    const float* W1   = nullptr;
    const float* W2   = nullptr;
    for (int i = 0; i < n_in; i++) {
        long s = in_sizes[i];
        if      (s == (long)NPTS * 64)      feat = (const float*)d_in[i];
        else if (s == (long)K27 * NPTS)     nbr  = (const int*)d_in[i];
        else if (s == (long)27 * 64 * 38)   W1   = (const float*)d_in[i];
        else if (s == (long)27 * 38 * 38)   W2   = (const float*)d_in[i];
    }
    float* out = (float*)d_out;
    __half *f16p, *hp;
    uint2 *w1p, *w2p;
    cudaGetSymbolAddress((void**)&f16p, g_f16);
    cudaGetSymbolAddress((void**)&hp,   g_h);
    cudaGetSymbolAddress((void**)&w1p,  g_W1f);
    cudaGetSymbolAddress((void**)&w2p,  g_W2f);

    const int smem1 = OFF_A + 3 * TM * (64 + 8) * 2;   // 35712 + 55296 = 91008
    const int smem2 = OFF_A + 3 * TM * (48 + 8) * 2;   // 35712 + 43008 = 78720
    cudaFuncSetAttribute(conv_mma<64, 4, true >, cudaFuncAttributeMaxDynamicSharedMemorySize, smem1);
    cudaFuncSetAttribute(conv_mma<48, 3, false>, cudaFuncAttributeMaxDynamicSharedMemorySize, smem2);

    cvt_feat<<<(NPTS * 64 / 4 + 255) / 256, 256>>>(feat);
    cvt_w<<<(27 * 5 * 4 * 32 + 255) / 256, 256>>>(W1, W2);
    conv_mma<64, 4, true ><<<NTILES, 256, smem1>>>(f16p, nbr, w1p, hp);
    conv_mma<48, 3, false><<<NTILES, 256, smem2>>>(hp,   nbr, w2p, out);
}

// round 7
// speedup vs baseline: 1.8932x; 1.8932x over previous
#include <cuda_runtime.h>
#include <cuda_fp16.h>
#include <math.h>
#include <stdint.h>

#define NPTS   400000
#define K27    27
#define TM     128
#define NTILES 3125     // 400000 / 128 exact

// ---------------- global scratch (static; no allocation allowed) ----------------
__device__ __half g_f16[(size_t)NPTS * 64];     // features fp16
__device__ __half g_h  [(size_t)NPTS * 48];     // layer-1 activations fp16, padded to 48
__device__ uint2  g_W1f[27 * 5 * 4 * 32];       // fragment-packed W1: [k][nb][ch][lane]
__device__ uint2  g_W2f[27 * 5 * 3 * 32];       // fragment-packed W2

// ---------------- fused sparse-conv layer, warp-owned register accumulation ----
// CIN: fp16 row width (64 or 48), KCH: k16 chunks (4 or 3)
template<int CIN, int KCH, bool DO_GELU>
__global__ void __launch_bounds__(256, 3) conv_reg(
    const __half* __restrict__ in, const int* __restrict__ nbr,
    const uint2* __restrict__ Wf, void* __restrict__ outp)
{
    __shared__ int sNbr[K27 * TM];

    const int tid  = threadIdx.x;
    const int lane = tid & 31;
    const int warp = tid >> 5;
    const int base = blockIdx.x * TM;

    // coalesced load of the tile's neighbor table
    #pragma unroll
    for (int e = tid; e < K27 * TM; e += 256)
        sNbr[e] = nbr[(size_t)(e >> 7) * NPTS + base + (e & 127)];
    __syncthreads();

    const int gid  = lane >> 2;      // fragment row group 0..7
    const int tg   = lane & 3;       // fragment col group 0..3
    const int row0 = warp * 16 + gid;
    const int row1 = row0 + 8;

    float D[5][4];
    #pragma unroll
    for (int nb = 0; nb < 5; nb++)
        #pragma unroll
        for (int j = 0; j < 4; j++) D[nb][j] = 0.0f;

    #pragma unroll 1
    for (int k = 0; k < K27; k++) {
        const int s0 = sNbr[k * TM + row0];
        const int s1 = sNbr[k * TM + row1];
        const bool v0 = (s0 != NPTS);
        const bool v1 = (s1 != NPTS);
        if (!__ballot_sync(0xFFFFFFFFu, v0 || v1)) continue;   // whole 16-row block empty

        const __half* p0 = in + (size_t)s0 * CIN + tg * 2;
        const __half* p1 = in + (size_t)s1 * CIN + tg * 2;

        // A fragments: predicated gather (zero rows for invalid neighbors)
        uint32_t A[KCH][4];
        #pragma unroll
        for (int ch = 0; ch < KCH; ch++) {
            const int off = ch * 16;
            A[ch][0] = v0 ? *(const uint32_t*)(p0 + off)     : 0u;
            A[ch][1] = v1 ? *(const uint32_t*)(p1 + off)     : 0u;
            A[ch][2] = v0 ? *(const uint32_t*)(p0 + off + 8) : 0u;
            A[ch][3] = v1 ? *(const uint32_t*)(p1 + off + 8) : 0u;
        }

        const uint2* wp = Wf + (size_t)k * 5 * KCH * 32 + lane;
        #pragma unroll
        for (int nb = 0; nb < 5; nb++) {
            #pragma unroll
            for (int ch = 0; ch < KCH; ch++) {
                const uint2 bb = wp[(nb * KCH + ch) * 32];
                asm volatile(
                    "mma.sync.aligned.m16n8k16.row.col.f32.f16.f16.f32 "
                    "{%0,%1,%2,%3}, {%4,%5,%6,%7}, {%8,%9}, {%0,%1,%2,%3};"
                    : "+f"(D[nb][0]), "+f"(D[nb][1]), "+f"(D[nb][2]), "+f"(D[nb][3])
                    : "r"(A[ch][0]), "r"(A[ch][1]), "r"(A[ch][2]), "r"(A[ch][3]),
                      "r"(bb.x), "r"(bb.y));
            }
        }
    }

    // ---- epilogue: fragments -> global, no staging ----
    const int r0 = base + row0;
    const int r1 = base + row1;
    if (DO_GELU) {
        uint32_t* hp = (uint32_t*)g_h;           // row stride 24 uint32 (48 halves)
        #pragma unroll
        for (int nb = 0; nb < 5; nb++) {
            const int cw = (nb * 8 + tg * 2) >> 1;   // uint32 column index
            float x0 = D[nb][0]; x0 *= normcdff(x0);
            float x1 = D[nb][1]; x1 *= normcdff(x1);
            float x2 = D[nb][2]; x2 *= normcdff(x2);
            float x3 = D[nb][3]; x3 *= normcdff(x3);
            __half2 h01 = __floats2half2_rn(x0, x1);
            __half2 h23 = __floats2half2_rn(x2, x3);
            hp[(size_t)r0 * 24 + cw] = *(uint32_t*)&h01;
            hp[(size_t)r1 * 24 + cw] = *(uint32_t*)&h23;
        }
        // zero pad columns 40..47 (uint32 cols 20..23)
        hp[(size_t)r0 * 24 + 20 + tg] = 0u;
        hp[(size_t)r1 * 24 + 20 + tg] = 0u;
    } else {
        float* op = (float*)outp;
        #pragma unroll
        for (int nb = 0; nb < 5; nb++) {
            const int col = nb * 8 + tg * 2;
            if (col < 38) {                       // skips only nb==4 && tg==3
                *(float2*)(op + (size_t)r0 * 38 + col) = make_float2(D[nb][0], D[nb][1]);
                *(float2*)(op + (size_t)r1 * 38 + col) = make_float2(D[nb][2], D[nb][3]);
            }
        }
    }
}

// ---------------- one-time conversions ----------------
__global__ void cvt_feat(const float* __restrict__ f) {
    size_t i = (size_t)blockIdx.x * blockDim.x + threadIdx.x;
    const size_t n4 = (size_t)NPTS * 64 / 4;
    if (i < n4) {
        float4 v = ((const float4*)f)[i];
        __half2* o = (__half2*)g_f16;
        o[i * 2 + 0] = __floats2half2_rn(v.x, v.y);
        o[i * 2 + 1] = __floats2half2_rn(v.z, v.w);
    }
}

// fragment packing: per (k, nb, ch, lane): n = nb*8 + lane/4, kk0 = ch*16 + (lane%4)*2
// b0 = (W[kk0][n], W[kk0+1][n]); b1 = (W[kk0+8][n], W[kk0+9][n])
template<int KW, int KCH>
__device__ __forceinline__ void pack_one(const float* W, uint2* Wf, int i) {
    int lane = i & 31, ch = (i >> 5) % KCH, nb = (i / (32 * KCH)) % 5, k = i / (32 * KCH * 5);
    int n = nb * 8 + (lane >> 2);
    int kk0 = ch * 16 + (lane & 3) * 2;
    const float* Wk = W + (size_t)k * KW * 38;
    auto val = [&](int kk) -> float {
        return (n < 38 && kk < KW) ? Wk[kk * 38 + n] : 0.0f;
    };
    __half2 b0 = __floats2half2_rn(val(kk0),     val(kk0 + 1));
    __half2 b1 = __floats2half2_rn(val(kk0 + 8), val(kk0 + 9));
    Wf[i] = make_uint2(*(uint32_t*)&b0, *(uint32_t*)&b1);
}
__global__ void cvt_w(const float* __restrict__ W1, const float* __restrict__ W2) {
    int i = blockIdx.x * blockDim.x + threadIdx.x;
    if (i < 27 * 5 * 4 * 32) pack_one<64, 4>(W1, g_W1f, i);
    if (i < 27 * 5 * 3 * 32) pack_one<38, 3>(W2, g_W2f, i);
}

extern "C" void kernel_launch(void* const* d_in, const int* in_sizes, int n_in,
                              void* d_out, int out_size)
{
    const float* feat = nullptr;
    const int*   nbr  = nullptr;
    const float* W1   = nullptr;
    const float* W2   = nullptr;
    for (int i = 0; i < n_in; i++) {
        long s = in_sizes[i];
        if      (s == (long)NPTS * 64)      feat = (const float*)d_in[i];
        else if (s == (long)K27 * NPTS)     nbr  = (const int*)d_in[i];
        else if (s == (long)27 * 64 * 38)   W1   = (const float*)d_in[i];
        else if (s == (long)27 * 38 * 38)   W2   = (const float*)d_in[i];
    }
    float* out = (float*)d_out;
    __half *f16p, *hp;
    uint2 *w1p, *w2p;
    cudaGetSymbolAddress((void**)&f16p, g_f16);
    cudaGetSymbolAddress((void**)&hp,   g_h);
    cudaGetSymbolAddress((void**)&w1p,  g_W1f);
    cudaGetSymbolAddress((void**)&w2p,  g_W2f);

    cvt_feat<<<(NPTS * 64 / 4 + 255) / 256, 256>>>(feat);
    cvt_w<<<(27 * 5 * 4 * 32 + 255) / 256, 256>>>(W1, W2);
    conv_reg<64, 4, true ><<<NTILES, 256>>>(f16p, nbr, w1p, hp);
    conv_reg<48, 3, false><<<NTILES, 256>>>(hp,   nbr, w2p, out);
}